// round 1
// baseline (speedup 1.0000x reference)
#include <cuda_runtime.h>
#include <math.h>

// Problem constants
#define NE 32
#define NT 2048
#define NH 1024
#define NI 512
#define NK 4
#define NP (NT*NK)   // 8192 (token, expert) pairs

#define BM 64
#define BN 64
#define BK 16

// ---- scratch (device globals; no allocation allowed) ----
__device__ int g_count[NE];
__device__ int g_off[NE+1];
__device__ int g_cursor[NE];
__device__ int g_tok[NP];     // token id per routed pair (grouped by expert)
__device__ int g_slot[NP];    // original t*NK+k slot per routed pair
__device__ float g_wt[NP];    // routing weight per pair
__device__ __align__(16) float g_h[(size_t)NP * NI];     // silu(gate)*up, 16 MB
__device__ __align__(16) float g_outp[(size_t)NP * NH];  // per-pair down output, 32 MB

// ---------------------------------------------------------------------------
// Routing: counting sort of the 8192 (t,k) pairs by expert.
// Order within an expert's list is non-deterministic (atomic cursor), but each
// pair's arithmetic is independent of its list position, and the final
// per-token reduction is done in fixed slot order -> deterministic output.
// ---------------------------------------------------------------------------
__global__ void route_kernel(const int* __restrict__ idx, const float* __restrict__ tw) {
    int tid = threadIdx.x;
    if (tid < NE) { g_count[tid] = 0; g_cursor[tid] = 0; }
    __syncthreads();
    for (int i = tid; i < NP; i += blockDim.x)
        atomicAdd(&g_count[idx[i]], 1);
    __syncthreads();
    if (tid == 0) {
        int s = 0;
        for (int e = 0; e < NE; e++) { g_off[e] = s; s += g_count[e]; }
        g_off[NE] = s;
    }
    __syncthreads();
    for (int i = tid; i < NP; i += blockDim.x) {
        int e = idx[i];
        int p = g_off[e] + atomicAdd(&g_cursor[e], 1);
        g_tok[p]  = i >> 2;   // i / NK
        g_slot[p] = i;
        g_wt[p]   = tw[i];
    }
}

// ---------------------------------------------------------------------------
// GEMM1: for expert e, rows = gathered tokens, compute gate & up tiles over
// K=H, fuse silu(gate)*up, write h into g_h[pair, NI].
// Block: 256 threads, 64x64 output tile (for BOTH gate and up), BK=16.
// ---------------------------------------------------------------------------
__global__ __launch_bounds__(256, 2) void gemm1_kernel(
    const float* __restrict__ X, const float* __restrict__ W)
{
    int e  = blockIdx.z;
    int n0 = g_off[e];
    int ne = g_off[e+1] - n0;
    int row0 = blockIdx.y * BM;
    if (row0 >= ne) return;
    int col0 = blockIdx.x * BN;

    __shared__ __align__(16) float sX[BK][BM+4];
    __shared__ __align__(16) float sG[BK][BN+4];
    __shared__ __align__(16) float sU[BK][BN+4];

    int tid = threadIdx.x;
    int tx = tid & 15, ty = tid >> 4;
    int lc = tid & 15, lr = tid >> 4;

    const float* Wg = W + (size_t)e * (2*NI) * NH;

    const float* xr[4]; const float* wg[4]; const float* wu[4];
    #pragma unroll
    for (int i = 0; i < 4; i++) {
        int r  = lr + 16*i;
        int rr = row0 + r;
        int t  = g_tok[n0 + (rr < ne ? rr : 0)];
        xr[i] = X + (size_t)t * NH;
        wg[i] = Wg + (size_t)(col0 + r) * NH;
        wu[i] = Wg + (size_t)(NI + col0 + r) * NH;
    }

    float accg[4][4] = {}, accu[4][4] = {};

    for (int kk = 0; kk < NH; kk += BK) {
        #pragma unroll
        for (int i = 0; i < 4; i++) {
            int r = lr + 16*i;
            sX[lc][r] = xr[i][kk + lc];
            sG[lc][r] = wg[i][kk + lc];
            sU[lc][r] = wu[i][kk + lc];
        }
        __syncthreads();
        #pragma unroll
        for (int k = 0; k < BK; k++) {
            float4 a  = *(const float4*)&sX[k][ty*4];
            float4 bg = *(const float4*)&sG[k][tx*4];
            float4 bu = *(const float4*)&sU[k][tx*4];
            float av[4]  = {a.x, a.y, a.z, a.w};
            float bgv[4] = {bg.x, bg.y, bg.z, bg.w};
            float buv[4] = {bu.x, bu.y, bu.z, bu.w};
            #pragma unroll
            for (int i2 = 0; i2 < 4; i2++)
                #pragma unroll
                for (int j = 0; j < 4; j++) {
                    accg[i2][j] += av[i2] * bgv[j];
                    accu[i2][j] += av[i2] * buv[j];
                }
        }
        __syncthreads();
    }

    #pragma unroll
    for (int i2 = 0; i2 < 4; i2++) {
        int r = row0 + ty*4 + i2;
        if (r >= ne) continue;
        size_t base = (size_t)(n0 + r) * NI + col0 + tx*4;
        #pragma unroll
        for (int j = 0; j < 4; j++) {
            float g = accg[i2][j];
            float u = accu[i2][j];
            float s = g / (1.f + __expf(-g));   // silu
            g_h[base + j] = s * u;
        }
    }
}

// ---------------------------------------------------------------------------
// GEMM2: out_pair = wt * (h @ Wd^T), written to slot-indexed staging buffer.
// ---------------------------------------------------------------------------
__global__ __launch_bounds__(256, 2) void gemm2_kernel(const float* __restrict__ Wd)
{
    int e  = blockIdx.z;
    int n0 = g_off[e];
    int ne = g_off[e+1] - n0;
    int row0 = blockIdx.y * BM;
    if (row0 >= ne) return;
    int col0 = blockIdx.x * BN;   // H columns

    __shared__ __align__(16) float sH[BK][BM+4];
    __shared__ __align__(16) float sW[BK][BN+4];

    int tid = threadIdx.x;
    int tx = tid & 15, ty = tid >> 4;
    int lc = tid & 15, lr = tid >> 4;

    const float* Wb = Wd + (size_t)e * NH * NI;

    const float* hr[4]; const float* wr[4];
    #pragma unroll
    for (int i = 0; i < 4; i++) {
        int r  = lr + 16*i;
        int rr = row0 + r;
        hr[i] = g_h + (size_t)(n0 + (rr < ne ? rr : 0)) * NI;
        wr[i] = Wb + (size_t)(col0 + r) * NI;
    }

    float acc[4][4] = {};

    for (int kk = 0; kk < NI; kk += BK) {
        #pragma unroll
        for (int i = 0; i < 4; i++) {
            int r = lr + 16*i;
            sH[lc][r] = hr[i][kk + lc];
            sW[lc][r] = wr[i][kk + lc];
        }
        __syncthreads();
        #pragma unroll
        for (int k = 0; k < BK; k++) {
            float4 a = *(const float4*)&sH[k][ty*4];
            float4 b = *(const float4*)&sW[k][tx*4];
            float av[4] = {a.x, a.y, a.z, a.w};
            float bv[4] = {b.x, b.y, b.z, b.w};
            #pragma unroll
            for (int i2 = 0; i2 < 4; i2++)
                #pragma unroll
                for (int j = 0; j < 4; j++)
                    acc[i2][j] += av[i2] * bv[j];
        }
        __syncthreads();
    }

    #pragma unroll
    for (int i2 = 0; i2 < 4; i2++) {
        int r = row0 + ty*4 + i2;
        if (r >= ne) continue;
        int p = n0 + r;
        float w = g_wt[p];
        size_t base = (size_t)g_slot[p] * NH + col0 + tx*4;
        #pragma unroll
        for (int j = 0; j < 4; j++)
            g_outp[base + j] = w * acc[i2][j];
    }
}

// ---------------------------------------------------------------------------
// Deterministic per-token reduction over the 4 top-k slots (fixed order).
// Every slot is written exactly once by gemm2, so no zero-init needed.
// ---------------------------------------------------------------------------
__global__ void reduce_kernel(float* __restrict__ out) {
    int idx4 = blockIdx.x * blockDim.x + threadIdx.x;
    if (idx4 >= NT * NH / 4) return;
    int t  = idx4 / (NH/4);
    int h4 = idx4 % (NH/4);
    float4 s = make_float4(0.f, 0.f, 0.f, 0.f);
    #pragma unroll
    for (int k = 0; k < NK; k++) {
        const float4 v = *(const float4*)&g_outp[(size_t)(t*NK + k) * NH + h4*4];
        s.x += v.x; s.y += v.y; s.z += v.z; s.w += v.w;
    }
    *(float4*)&out[(size_t)t * NH + h4*4] = s;
}

// ---------------------------------------------------------------------------
extern "C" void kernel_launch(void* const* d_in, const int* in_sizes, int n_in,
                              void* d_out, int out_size)
{
    const float* X    = (const float*)d_in[0];  // hidden_states [T,H]
    const int*   idx  = (const int*)  d_in[1];  // top_k_index [T,K]
    const float* tw   = (const float*)d_in[2];  // top_k_weights [T,K]
    const float* gup  = (const float*)d_in[3];  // gate_up_proj [E,2I,H]
    const float* down = (const float*)d_in[4];  // down_proj [E,H,I]
    float* out = (float*)d_out;                 // [T,H]

    route_kernel<<<1, 256>>>(idx, tw);
    gemm1_kernel<<<dim3(NI/BN, NP/BM, NE), 256>>>(X, gup);
    gemm2_kernel<<<dim3(NH/BN, NP/BM, NE), 256>>>(down);
    reduce_kernel<<<(NT*NH/4 + 255)/256, 256>>>(out);
}

// round 2
// speedup vs baseline: 2.3319x; 2.3319x over previous
#include <cuda_runtime.h>
#include <math.h>
#include <stdint.h>

// Problem constants
#define NE 32
#define NT 2048
#define NH 1024
#define NI 512
#define NK 4
#define NP (NT*NK)   // 8192 routed pairs

#define BM 128
#define BN 64
#define BK 16
#define MAXT 96      // max row-tiles across all experts: 8192/128 + 31 < 96

// ---- scratch (device globals) ----
__device__ int g_off[NE+1];
__device__ int g_count[NE];
__device__ int g_cursor[NE];
__device__ int g_tok[NP];
__device__ int g_slot[NP];
__device__ float g_wt[NP];
__device__ int g_tile_e[MAXT];
__device__ int g_tile_r[MAXT];
__device__ int g_ntile;
__device__ __align__(16) float g_h[(size_t)NP * NI];     // 16 MB
__device__ __align__(16) float g_outp[(size_t)NP * NH];  // 32 MB

// ---------------- PTX helpers ----------------
__device__ __forceinline__ uint32_t f2tf(float f) {
    uint32_t r; asm("cvt.rna.tf32.f32 %0, %1;\n" : "=r"(r) : "f"(f)); return r;
}
__device__ __forceinline__ void mma_tf32(float c[4], const uint32_t a[4],
                                         uint32_t b0, uint32_t b1) {
    asm volatile(
        "mma.sync.aligned.m16n8k8.row.col.f32.tf32.tf32.f32 "
        "{%0,%1,%2,%3}, {%4,%5,%6,%7}, {%8,%9}, {%0,%1,%2,%3};\n"
        : "+f"(c[0]), "+f"(c[1]), "+f"(c[2]), "+f"(c[3])
        : "r"(a[0]), "r"(a[1]), "r"(a[2]), "r"(a[3]), "r"(b0), "r"(b1));
}
__device__ __forceinline__ void cp16(void* smem, const void* gmem) {
    uint32_t s = (uint32_t)__cvta_generic_to_shared(smem);
    asm volatile("cp.async.cg.shared.global [%0], [%1], 16;\n" :: "r"(s), "l"(gmem));
}
#define CP_COMMIT asm volatile("cp.async.commit_group;\n")
#define CP_WAIT1  asm volatile("cp.async.wait_group 1;\n")
#define CP_WAIT0  asm volatile("cp.async.wait_group 0;\n")

// ---------------------------------------------------------------------------
// Routing: counting sort by expert + tile list. Output order within an expert
// is atomic (non-deterministic) but every pair's math is position-independent
// and the final reduce is in fixed slot order -> deterministic result.
// ---------------------------------------------------------------------------
__global__ void route_kernel(const int* __restrict__ idx, const float* __restrict__ tw) {
    int tid = threadIdx.x;
    if (tid < NE) { g_count[tid] = 0; g_cursor[tid] = 0; }
    __syncthreads();
    for (int i = tid; i < NP; i += blockDim.x)
        atomicAdd(&g_count[idx[i]], 1);
    __syncthreads();
    if (tid == 0) {
        int s = 0, nt = 0;
        for (int e = 0; e < NE; e++) {
            g_off[e] = s;
            int c = g_count[e];
            for (int r0 = 0; r0 < c; r0 += BM) { g_tile_e[nt] = e; g_tile_r[nt] = r0; nt++; }
            s += c;
        }
        g_off[NE] = s;
        g_ntile = nt;
    }
    __syncthreads();
    for (int i = tid; i < NP; i += blockDim.x) {
        int e = idx[i];
        int p = g_off[e] + atomicAdd(&g_cursor[e], 1);
        g_tok[p]  = i >> 2;
        g_slot[p] = i;
        g_wt[p]   = tw[i];
    }
}

// ---------------------------------------------------------------------------
// GEMM1 (tf32 HMMA): gathered tokens x gate_up weights, fused silu*up.
// CTA tile 128 rows x (64 gate + 64 up cols), BK=16, 2-stage cp.async.
// ---------------------------------------------------------------------------
__global__ __launch_bounds__(256) void gemm1_kernel(
    const float* __restrict__ X, const float* __restrict__ W)
{
    int by = blockIdx.y;
    if (by >= g_ntile) return;
    int e = g_tile_e[by], row0 = g_tile_r[by];
    int n0 = g_off[e], ne = g_off[e+1] - n0;
    int col0 = blockIdx.x * BN;

    __shared__ __align__(16) float sX[2][BM][BK+4];
    __shared__ __align__(16) float sG[2][BN][BK+4];
    __shared__ __align__(16) float sU[2][BN][BK+4];

    int tid = threadIdx.x;
    // A loader: row = tid>>1, 8 consecutive floats (2x float4) at (tid&1)*8
    int arow = tid >> 1;
    int acol = (tid & 1) * 8;
    int grow = row0 + arow;
    int tok = g_tok[n0 + (grow < ne ? grow : 0)];
    const float* pA = X + (size_t)tok * NH + acol;
    // B loader: row = tid>>2, float4 at (tid&3)*4
    int brow = tid >> 2;
    int bcol = (tid & 3) * 4;
    const float* Wg = W + (size_t)e * (2*NI) * NH;
    const float* pG = Wg + (size_t)(col0 + brow) * NH + bcol;
    const float* pU = Wg + (size_t)(NI + col0 + brow) * NH + bcol;

    int wid = tid >> 5, lane = tid & 31;
    int wm = (wid & 3) * 32;          // 4 warps along M
    int wn = (wid >> 2) * 32;         // 2 warps along N
    int gid = lane >> 2, tig = lane & 3;

    float ag[2][4][4] = {}, au[2][4][4] = {};

    #define LOAD_STAGE1(s, kk) do {                       \
        cp16(&sX[s][arow][acol],     pA + (kk));          \
        cp16(&sX[s][arow][acol+4],   pA + (kk) + 4);      \
        cp16(&sG[s][brow][bcol],     pG + (kk));          \
        cp16(&sU[s][brow][bcol],     pU + (kk));          \
    } while (0)

    const int NIT = NH / BK;   // 64
    LOAD_STAGE1(0, 0);
    CP_COMMIT;

    for (int it = 0; it < NIT; it++) {
        if (it + 1 < NIT) { LOAD_STAGE1((it+1)&1, (it+1)*BK); CP_COMMIT; CP_WAIT1; }
        else              { CP_WAIT0; }
        __syncthreads();
        int s = it & 1;
        #pragma unroll
        for (int k8 = 0; k8 < 2; k8++) {
            int ko = k8*8 + tig;
            uint32_t a[2][4];
            #pragma unroll
            for (int i = 0; i < 2; i++) {
                int r = wm + i*16 + gid;
                a[i][0] = f2tf(sX[s][r  ][ko  ]);
                a[i][1] = f2tf(sX[s][r+8][ko  ]);
                a[i][2] = f2tf(sX[s][r  ][ko+4]);
                a[i][3] = f2tf(sX[s][r+8][ko+4]);
            }
            #pragma unroll
            for (int j = 0; j < 4; j++) {
                int n = wn + j*8 + gid;
                uint32_t bg0 = f2tf(sG[s][n][ko]),  bg1 = f2tf(sG[s][n][ko+4]);
                uint32_t bu0 = f2tf(sU[s][n][ko]),  bu1 = f2tf(sU[s][n][ko+4]);
                #pragma unroll
                for (int i = 0; i < 2; i++) {
                    mma_tf32(ag[i][j], a[i], bg0, bg1);
                    mma_tf32(au[i][j], a[i], bu0, bu1);
                }
            }
        }
        __syncthreads();
    }

    // Epilogue: silu(gate) * up -> g_h
    #pragma unroll
    for (int i = 0; i < 2; i++) {
        #pragma unroll
        for (int h = 0; h < 2; h++) {
            int r = row0 + wm + i*16 + gid + h*8;
            if (r >= ne) continue;
            size_t rb = (size_t)(n0 + r) * NI + col0 + wn + 2*tig;
            #pragma unroll
            for (int j = 0; j < 4; j++) {
                float g0 = ag[i][j][h*2], g1 = ag[i][j][h*2+1];
                float u0 = au[i][j][h*2], u1 = au[i][j][h*2+1];
                float v0 = g0 / (1.f + __expf(-g0)) * u0;
                float v1 = g1 / (1.f + __expf(-g1)) * u1;
                *(float2*)&g_h[rb + j*8] = make_float2(v0, v1);
            }
        }
    }
}

// ---------------------------------------------------------------------------
// GEMM2 (tf32 HMMA): h @ down^T, scaled by routing weight, scattered by slot.
// ---------------------------------------------------------------------------
__global__ __launch_bounds__(256) void gemm2_kernel(const float* __restrict__ Wd)
{
    int by = blockIdx.y;
    if (by >= g_ntile) return;
    int e = g_tile_e[by], row0 = g_tile_r[by];
    int n0 = g_off[e], ne = g_off[e+1] - n0;
    int col0 = blockIdx.x * BN;

    __shared__ __align__(16) float sH[2][BM][BK+4];
    __shared__ __align__(16) float sW[2][BN][BK+4];

    int tid = threadIdx.x;
    int arow = tid >> 1;
    int acol = (tid & 1) * 8;
    int grow = row0 + arow;
    const float* pA = g_h + (size_t)(n0 + (grow < ne ? grow : 0)) * NI + acol;
    int brow = tid >> 2;
    int bcol = (tid & 3) * 4;
    const float* pB = Wd + (size_t)e * NH * NI + (size_t)(col0 + brow) * NI + bcol;

    int wid = tid >> 5, lane = tid & 31;
    int wm = (wid & 3) * 32;
    int wn = (wid >> 2) * 32;
    int gid = lane >> 2, tig = lane & 3;

    float acc[2][4][4] = {};

    #define LOAD_STAGE2(s, kk) do {                       \
        cp16(&sH[s][arow][acol],     pA + (kk));          \
        cp16(&sH[s][arow][acol+4],   pA + (kk) + 4);      \
        cp16(&sW[s][brow][bcol],     pB + (kk));          \
    } while (0)

    const int NIT = NI / BK;   // 32
    LOAD_STAGE2(0, 0);
    CP_COMMIT;

    for (int it = 0; it < NIT; it++) {
        if (it + 1 < NIT) { LOAD_STAGE2((it+1)&1, (it+1)*BK); CP_COMMIT; CP_WAIT1; }
        else              { CP_WAIT0; }
        __syncthreads();
        int s = it & 1;
        #pragma unroll
        for (int k8 = 0; k8 < 2; k8++) {
            int ko = k8*8 + tig;
            uint32_t a[2][4];
            #pragma unroll
            for (int i = 0; i < 2; i++) {
                int r = wm + i*16 + gid;
                a[i][0] = f2tf(sH[s][r  ][ko  ]);
                a[i][1] = f2tf(sH[s][r+8][ko  ]);
                a[i][2] = f2tf(sH[s][r  ][ko+4]);
                a[i][3] = f2tf(sH[s][r+8][ko+4]);
            }
            #pragma unroll
            for (int j = 0; j < 4; j++) {
                int n = wn + j*8 + gid;
                uint32_t b0 = f2tf(sW[s][n][ko]), b1 = f2tf(sW[s][n][ko+4]);
                #pragma unroll
                for (int i = 0; i < 2; i++)
                    mma_tf32(acc[i][j], a[i], b0, b1);
            }
        }
        __syncthreads();
    }

    #pragma unroll
    for (int i = 0; i < 2; i++) {
        #pragma unroll
        for (int h = 0; h < 2; h++) {
            int r = row0 + wm + i*16 + gid + h*8;
            if (r >= ne) continue;
            int p = n0 + r;
            float w = g_wt[p];
            size_t rb = (size_t)g_slot[p] * NH + col0 + wn + 2*tig;
            #pragma unroll
            for (int j = 0; j < 4; j++) {
                float v0 = w * acc[i][j][h*2];
                float v1 = w * acc[i][j][h*2+1];
                *(float2*)&g_outp[rb + j*8] = make_float2(v0, v1);
            }
        }
    }
}

// ---------------------------------------------------------------------------
// Deterministic per-token reduction over the 4 slots (fixed order).
// ---------------------------------------------------------------------------
__global__ void reduce_kernel(float* __restrict__ out) {
    int idx4 = blockIdx.x * blockDim.x + threadIdx.x;
    if (idx4 >= NT * NH / 4) return;
    int t  = idx4 / (NH/4);
    int h4 = idx4 % (NH/4);
    float4 s = make_float4(0.f, 0.f, 0.f, 0.f);
    #pragma unroll
    for (int k = 0; k < NK; k++) {
        const float4 v = *(const float4*)&g_outp[(size_t)(t*NK + k) * NH + h4*4];
        s.x += v.x; s.y += v.y; s.z += v.z; s.w += v.w;
    }
    *(float4*)&out[(size_t)t * NH + h4*4] = s;
}

// ---------------------------------------------------------------------------
extern "C" void kernel_launch(void* const* d_in, const int* in_sizes, int n_in,
                              void* d_out, int out_size)
{
    const float* X    = (const float*)d_in[0];
    const int*   idx  = (const int*)  d_in[1];
    const float* tw   = (const float*)d_in[2];
    const float* gup  = (const float*)d_in[3];
    const float* down = (const float*)d_in[4];
    float* out = (float*)d_out;

    route_kernel<<<1, 256>>>(idx, tw);
    gemm1_kernel<<<dim3(NI/BN,  MAXT), 256>>>(X, gup);
    gemm2_kernel<<<dim3(NH/BN,  MAXT), 256>>>(down);
    reduce_kernel<<<(NT*NH/4 + 255)/256, 256>>>(out);
}